// round 10
// baseline (speedup 1.0000x reference)
#include <cuda_runtime.h>

// LSTM_584115552367: B=65536 independent LSTMs, D=H=17, T=50, SLB=30.
// R9: 2 elements/thread (weight LDS amortized 2x) + R6 coalesced staging +
// R5 j-pair core (8 LDS.128 batched -> now 16 acc chains / 32 fma2 per batch).
// Register-disciplined: __launch_bounds__(64,5) -> 204-reg cap (est. peak ~189).

#define BSZ   65536
#define TLEN  50
#define DDIM  17
#define SLBC  30
#define NP    9            // padded d-pairs (18/2)
#define TPB   64
#define EPC   (2 * TPB)    // elements per CTA = 128
#define TOUT  (TLEN - SLBC)
#define XROW  18           // staging row stride (floats), 8B-aligned rows

typedef unsigned long long u64;

__device__ __forceinline__ u64 pack2(float lo, float hi) {
    u64 r; asm("mov.b64 %0, {%1, %2};" : "=l"(r) : "f"(lo), "f"(hi)); return r;
}
__device__ __forceinline__ void unpack2(u64 v, float &lo, float &hi) {
    asm("mov.b64 {%0, %1}, %2;" : "=f"(lo), "=f"(hi) : "l"(v));
}
__device__ __forceinline__ void fma2a(u64 &acc, u64 a, u64 b) {
    asm("fma.rn.f32x2 %0, %1, %2, %0;" : "+l"(acc) : "l"(a), "l"(b));
}
__device__ __forceinline__ float hadd2(u64 v) {
    float a, b; unpack2(v, a, b); return a + b;
}

__device__ __forceinline__ float ex2f(float x) {
    float r; asm("ex2.approx.f32 %0, %1;" : "=f"(r) : "f"(x)); return r;
}
__device__ __forceinline__ float rcpf(float x) {
    float r; asm("rcp.approx.f32 %0, %1;" : "=f"(r) : "f"(x)); return r;
}
// sigmoid(x) = 1 / (1 + 2^(-x*log2e)); safe at both extremes (rcp(inf)=0).
__device__ __forceinline__ float sigm(float x) {
    return rcpf(1.0f + ex2f(-1.4426950408889634f * x));
}
// tanh(x) = sign(x)*(1-e)/(1+e), e = 2^(-2|x|*log2e); e<=1, no inf/NaN.
__device__ __forceinline__ float tanhx(float x) {
    float ax = fabsf(x);
    float e  = ex2f(-2.8853900817779268f * ax);
    float r  = (1.0f - e) * rcpf(1.0f + e);
    return copysignf(r, x);
}

__global__ void __launch_bounds__(TPB, 5) lstm_kernel(
    const float* __restrict__ x,     // [B, T, D]
    const float* __restrict__ Wih,   // [4D, D]
    const float* __restrict__ Whh,   // [4D, D]
    const float* __restrict__ bih,   // [4D]
    const float* __restrict__ bhh,   // [4D]
    const float* __restrict__ Wlin,  // [D, D]
    const float* __restrict__ blin,  // [D]
    const float* __restrict__ mih,   // [4D, D]
    const float* __restrict__ mhh,   // [4D, D]
    float* __restrict__ out)         // [B, TOUT, D]
{
    __shared__ ulonglong2 sWq[DDIM * NP * 4];
    __shared__ ulonglong2 sB[DDIM * 2];
    __shared__ ulonglong2 sLin2[NP * NP];
    __shared__ u64 sBlin[2 * NP];
    __shared__ float sStage[EPC * XROW];   // x / out staging, 18-float row per element

    for (int idx = threadIdx.x; idx < DDIM * NP * 4; idx += TPB) {
        int j = idx / 36, r = idx % 36, p = r / 4, q = r % 4;
        const float* W = (q < 2) ? Wih : Whh;
        const float* M = (q < 2) ? mih : mhh;
        int gA = (q & 1) ? (34 + j) : j;
        int gB = (q & 1) ? (51 + j) : (17 + j);
        int d0 = 2 * p, d1 = 2 * p + 1;
        float a0 = W[gA * DDIM + d0] * M[gA * DDIM + d0];
        float a1 = (d1 < DDIM) ? W[gA * DDIM + d1] * M[gA * DDIM + d1] : 0.0f;
        float b0 = W[gB * DDIM + d0] * M[gB * DDIM + d0];
        float b1 = (d1 < DDIM) ? W[gB * DDIM + d1] * M[gB * DDIM + d1] : 0.0f;
        ulonglong2 v; v.x = pack2(a0, a1); v.y = pack2(b0, b1);
        sWq[idx] = v;
    }
    for (int idx = threadIdx.x; idx < NP * NP; idx += TPB) {
        int ccp = idx / NP, p = idx % NP;
        int c0 = 2 * ccp, c1 = 2 * ccp + 1;
        int d0 = 2 * p, d1 = 2 * p + 1;
        float x0 = Wlin[c0 * DDIM + d0];
        float x1 = (d1 < DDIM) ? Wlin[c0 * DDIM + d1] : 0.0f;
        float y0 = (c1 < DDIM) ? Wlin[c1 * DDIM + d0] : 0.0f;
        float y1 = (c1 < DDIM && d1 < DDIM) ? Wlin[c1 * DDIM + d1] : 0.0f;
        ulonglong2 v; v.x = pack2(x0, x1); v.y = pack2(y0, y1);
        sLin2[idx] = v;
    }
    if (threadIdx.x < DDIM) {
        int j = threadIdx.x;
        ulonglong2 v0, v1;
        v0.x = pack2(bih[j]      + bhh[j],      0.0f);
        v0.y = pack2(bih[17 + j] + bhh[17 + j], 0.0f);
        v1.x = pack2(bih[34 + j] + bhh[34 + j], 0.0f);
        v1.y = pack2(bih[51 + j] + bhh[51 + j], 0.0f);
        sB[2 * j] = v0; sB[2 * j + 1] = v1;
    }
    if (threadIdx.x < 2 * NP) {
        int cc = threadIdx.x;
        sBlin[cc] = (cc < DDIM) ? pack2(blin[cc], 0.0f) : 0ull;
    }
    __syncthreads();

    const int tid = threadIdx.x;
    // CTA covers EPC=128 elements; this thread owns elements tid and tid+64.
    const long bi0 = (long)blockIdx.x * EPC;
    const float* __restrict__ xg = x + bi0 * (TLEN * DDIM);      // CTA x base
    float* __restrict__ og = out + bi0 * (TOUT * DDIM);          // CTA out base
    const u64* __restrict__ sRowA = (const u64*)(sStage + tid * XROW);
    const u64* __restrict__ sRowB = (const u64*)(sStage + (tid + TPB) * XROW);

    u64 xiA[NP], xiB[NP], hA[NP], hB[NP], hnA[NP], hnB[NP];
    float cA[DDIM], cB[DDIM];
#pragma unroll
    for (int p = 0; p < NP; p++) { xiA[p] = 0ull; xiB[p] = 0ull; hA[p] = 0ull; hB[p] = 0ull; }
#pragma unroll
    for (int j = 0; j < DDIM; j++) { cA[j] = 0.0f; cB[j] = 0.0f; }

#pragma unroll 1
    for (int t = 0; t < TLEN; t++) {
        if (t < SLBC) {
            __syncthreads();   // staging buffer free (prior readers done)
            // Coalesced cooperative load: 128*17 floats for this CTA at step t.
#pragma unroll
            for (int k = 0; k < 2 * DDIM; k++) {
                int idx = tid + k * TPB;             // 0..2175, warp-consecutive
                int el = idx / DDIM, d = idx % DDIM;
                sStage[el * XROW + d] = xg[(long)el * (TLEN * DDIM) + t * DDIM + d];
            }
            __syncthreads();
#pragma unroll
            for (int p = 0; p < 8; p++) { xiA[p] = sRowA[p]; xiB[p] = sRowB[p]; }
            {
                float lo, hi;
                unpack2(sRowA[8], lo, hi); xiA[8] = pack2(lo, 0.0f);
                unpack2(sRowB[8], lo, hi); xiB[8] = pack2(lo, 0.0f);
            }
        }

        // ---- LSTM cell: j-pairs, weights shared across both elements (16 chains) ----
#pragma unroll
        for (int jj = 0; jj < 8; jj++) {
            const int j0 = 2 * jj, j1 = 2 * jj + 1;
            ulonglong2 b00 = sB[2 * j0], b01 = sB[2 * j0 + 1];
            ulonglong2 b10 = sB[2 * j1], b11 = sB[2 * j1 + 1];
            u64 ai0A = b00.x, af0A = b00.y, ag0A = b01.x, ao0A = b01.y;
            u64 ai1A = b10.x, af1A = b10.y, ag1A = b11.x, ao1A = b11.y;
            u64 ai0B = b00.x, af0B = b00.y, ag0B = b01.x, ao0B = b01.y;
            u64 ai1B = b10.x, af1B = b10.y, ag1B = b11.x, ao1B = b11.y;
#pragma unroll
            for (int p = 0; p < NP; p++) {
                ulonglong2 w00 = sWq[(j0 * NP + p) * 4 + 0];
                ulonglong2 w01 = sWq[(j0 * NP + p) * 4 + 1];
                ulonglong2 w02 = sWq[(j0 * NP + p) * 4 + 2];
                ulonglong2 w03 = sWq[(j0 * NP + p) * 4 + 3];
                ulonglong2 w10 = sWq[(j1 * NP + p) * 4 + 0];
                ulonglong2 w11 = sWq[(j1 * NP + p) * 4 + 1];
                ulonglong2 w12 = sWq[(j1 * NP + p) * 4 + 2];
                ulonglong2 w13 = sWq[(j1 * NP + p) * 4 + 3];
                u64 xa = xiA[p], ha = hA[p];
                u64 xb = xiB[p], hb = hB[p];
                fma2a(ai0A, xa, w00.x); fma2a(af0A, xa, w00.y);
                fma2a(ag0A, xa, w01.x); fma2a(ao0A, xa, w01.y);
                fma2a(ai1A, xa, w10.x); fma2a(af1A, xa, w10.y);
                fma2a(ag1A, xa, w11.x); fma2a(ao1A, xa, w11.y);
                fma2a(ai0B, xb, w00.x); fma2a(af0B, xb, w00.y);
                fma2a(ag0B, xb, w01.x); fma2a(ao0B, xb, w01.y);
                fma2a(ai1B, xb, w10.x); fma2a(af1B, xb, w10.y);
                fma2a(ag1B, xb, w11.x); fma2a(ao1B, xb, w11.y);
                fma2a(ai0A, ha, w02.x); fma2a(af0A, ha, w02.y);
                fma2a(ag0A, ha, w03.x); fma2a(ao0A, ha, w03.y);
                fma2a(ai1A, ha, w12.x); fma2a(af1A, ha, w12.y);
                fma2a(ag1A, ha, w13.x); fma2a(ao1A, ha, w13.y);
                fma2a(ai0B, hb, w02.x); fma2a(af0B, hb, w02.y);
                fma2a(ag0B, hb, w03.x); fma2a(ao0B, hb, w03.y);
                fma2a(ai1B, hb, w12.x); fma2a(af1B, hb, w12.y);
                fma2a(ag1B, hb, w13.x); fma2a(ao1B, hb, w13.y);
            }
            float hn0, hn1;
            {
                float gi = hadd2(ai0A), gf = hadd2(af0A), gg = hadd2(ag0A), go = hadd2(ao0A);
                float cn = fmaf(sigm(gf), cA[j0], sigm(gi) * tanhx(gg));
                cA[j0] = cn; hn0 = sigm(go) * tanhx(cn);
            }
            {
                float gi = hadd2(ai1A), gf = hadd2(af1A), gg = hadd2(ag1A), go = hadd2(ao1A);
                float cn = fmaf(sigm(gf), cA[j1], sigm(gi) * tanhx(gg));
                cA[j1] = cn; hn1 = sigm(go) * tanhx(cn);
            }
            hnA[jj] = pack2(hn0, hn1);
            {
                float gi = hadd2(ai0B), gf = hadd2(af0B), gg = hadd2(ag0B), go = hadd2(ao0B);
                float cn = fmaf(sigm(gf), cB[j0], sigm(gi) * tanhx(gg));
                cB[j0] = cn; hn0 = sigm(go) * tanhx(cn);
            }
            {
                float gi = hadd2(ai1B), gf = hadd2(af1B), gg = hadd2(ag1B), go = hadd2(ao1B);
                float cn = fmaf(sigm(gf), cB[j1], sigm(gi) * tanhx(gg));
                cB[j1] = cn; hn1 = sigm(go) * tanhx(cn);
            }
            hnB[jj] = pack2(hn0, hn1);
        }
        {   // tail j = 16
            const int j = 16;
            ulonglong2 b0 = sB[2 * j], b1 = sB[2 * j + 1];
            u64 aiA = b0.x, afA = b0.y, agA = b1.x, aoA = b1.y;
            u64 aiB = b0.x, afB = b0.y, agB = b1.x, aoB = b1.y;
#pragma unroll
            for (int p = 0; p < NP; p++) {
                ulonglong2 w0 = sWq[(j * NP + p) * 4 + 0];
                ulonglong2 w1 = sWq[(j * NP + p) * 4 + 1];
                ulonglong2 w2 = sWq[(j * NP + p) * 4 + 2];
                ulonglong2 w3 = sWq[(j * NP + p) * 4 + 3];
                u64 xa = xiA[p], ha = hA[p];
                u64 xb = xiB[p], hb = hB[p];
                fma2a(aiA, xa, w0.x); fma2a(afA, xa, w0.y);
                fma2a(agA, xa, w1.x); fma2a(aoA, xa, w1.y);
                fma2a(aiB, xb, w0.x); fma2a(afB, xb, w0.y);
                fma2a(agB, xb, w1.x); fma2a(aoB, xb, w1.y);
                fma2a(aiA, ha, w2.x); fma2a(afA, ha, w2.y);
                fma2a(agA, ha, w3.x); fma2a(aoA, ha, w3.y);
                fma2a(aiB, hb, w2.x); fma2a(afB, hb, w2.y);
                fma2a(agB, hb, w3.x); fma2a(aoB, hb, w3.y);
            }
            {
                float gi = hadd2(aiA), gf = hadd2(afA), gg = hadd2(agA), go = hadd2(aoA);
                float cn = fmaf(sigm(gf), cA[j], sigm(gi) * tanhx(gg));
                cA[j] = cn; hnA[8] = pack2(sigm(go) * tanhx(cn), 0.0f);
            }
            {
                float gi = hadd2(aiB), gf = hadd2(afB), gg = hadd2(agB), go = hadd2(aoB);
                float cn = fmaf(sigm(gf), cB[j], sigm(gi) * tanhx(gg));
                cB[j] = cn; hnB[8] = pack2(sigm(go) * tanhx(cn), 0.0f);
            }
        }
#pragma unroll
        for (int p = 0; p < NP; p++) { hA[p] = hnA[p]; hB[p] = hnB[p]; }

        if (t >= SLBC - 1) {
            float oA[2 * NP], oB[2 * NP];
#pragma unroll
            for (int ccp = 0; ccp < NP; ccp++) {
                u64 a0A = sBlin[2 * ccp], a1A = sBlin[2 * ccp + 1];
                u64 a0B = a0A, a1B = a1A;
#pragma unroll
                for (int p = 0; p < NP; p++) {
                    ulonglong2 w = sLin2[ccp * NP + p];
                    fma2a(a0A, hA[p], w.x); fma2a(a1A, hA[p], w.y);
                    fma2a(a0B, hB[p], w.x); fma2a(a1B, hB[p], w.y);
                }
                oA[2 * ccp] = hadd2(a0A); oA[2 * ccp + 1] = hadd2(a1A);
                oB[2 * ccp] = hadd2(a0B); oB[2 * ccp + 1] = hadd2(a1B);
            }
            if (t >= SLBC) {
                int tp = t - SLBC;
                __syncthreads();   // buffer free (prior step's STG readers done)
                u64* rowA = (u64*)(sStage + tid * XROW);
                u64* rowB = (u64*)(sStage + (tid + TPB) * XROW);
#pragma unroll
                for (int p = 0; p < NP; p++) {
                    rowA[p] = pack2(oA[2 * p], (2 * p + 1 < DDIM) ? oA[2 * p + 1] : 0.0f);
                    rowB[p] = pack2(oB[2 * p], (2 * p + 1 < DDIM) ? oB[2 * p + 1] : 0.0f);
                }
                __syncthreads();
                // Coalesced cooperative store of this step's 128*17 outputs.
#pragma unroll
                for (int k = 0; k < 2 * DDIM; k++) {
                    int idx = tid + k * TPB;
                    int el = idx / DDIM, d = idx % DDIM;
                    og[(long)el * (TOUT * DDIM) + tp * DDIM + d] = sStage[el * XROW + d];
                }
            }
            // Feedback input for next step.
#pragma unroll
            for (int p = 0; p < 8; p++) {
                xiA[p] = pack2(oA[2 * p], oA[2 * p + 1]);
                xiB[p] = pack2(oB[2 * p], oB[2 * p + 1]);
            }
            xiA[8] = pack2(oA[16], 0.0f);
            xiB[8] = pack2(oB[16], 0.0f);
        }
    }
}

extern "C" void kernel_launch(void* const* d_in, const int* in_sizes, int n_in,
                              void* d_out, int out_size) {
    const float* x    = (const float*)d_in[0];
    const float* Wih  = (const float*)d_in[1];
    const float* Whh  = (const float*)d_in[2];
    const float* bih  = (const float*)d_in[3];
    const float* bhh  = (const float*)d_in[4];
    const float* Wlin = (const float*)d_in[5];
    const float* blin = (const float*)d_in[6];
    const float* mih  = (const float*)d_in[7];
    const float* mhh  = (const float*)d_in[8];
    float* out = (float*)d_out;

    dim3 grid(BSZ / EPC);   // 512 CTAs of 64 threads, 2 elements/thread
    dim3 block(TPB);
    lstm_kernel<<<grid, block>>>(x, Wih, Whh, bih, bhh, Wlin, blin, mih, mhh, out);
}

// round 11
// speedup vs baseline: 1.3096x; 1.3096x over previous
#include <cuda_runtime.h>

// LSTM_584115552367: B=65536 independent LSTMs, D=H=17, T=50, SLB=30.
// R10: R6 core (best, 689.7us) with ALL weight/bias tables moved from SMEM to
// __constant__ memory. Warp-uniform, compile-time-offset reads -> LDCU uniform
// port (floor 1/cyc, separate from LSU) -> l1tex wavefront pipe (the measured
// 70.6% bottleneck) is freed. Prep kernel packs weights -> __device__ buffer ->
// cudaMemcpyToSymbolAsync (D2D, graph-capturable) -> main kernel.

#define BSZ   65536
#define TLEN  50
#define DDIM  17
#define SLBC  30
#define NP    9            // padded d-pairs (18/2)
#define TPB   64
#define TOUT  (TLEN - SLBC)
#define XROW  18           // staging row stride (floats), 8B-aligned rows

// constant buffer layout (u64 units)
#define OFF_W    0                       // gate weights: ((j*9+p)*4+q)*2+h, 1224 u64
#define OFF_B    1224                    // biases: j*4 + {i,f,g,o}, 68 u64
#define OFF_LIN  1292                    // lin: ((ccp*9+p))*2+h, 162 u64
#define OFF_BLIN 1454                    // blin: cc, 18 u64
#define CBUF_N   1472

typedef unsigned long long u64;

__device__   u64 g_wbuf[CBUF_N];
__constant__ u64 cbuf[CBUF_N];

#define CW(j,p,q,h)  cbuf[OFF_W + (((j)*9 + (p))*4 + (q))*2 + (h)]
#define CB(j,g)      cbuf[OFF_B + (j)*4 + (g)]
#define CL(ccp,p,h)  cbuf[OFF_LIN + ((ccp)*9 + (p))*2 + (h)]
#define CBL(cc)      cbuf[OFF_BLIN + (cc)]

__device__ __forceinline__ u64 pack2(float lo, float hi) {
    u64 r; asm("mov.b64 %0, {%1, %2};" : "=l"(r) : "f"(lo), "f"(hi)); return r;
}
__device__ __forceinline__ void unpack2(u64 v, float &lo, float &hi) {
    asm("mov.b64 {%0, %1}, %2;" : "=f"(lo), "=f"(hi) : "l"(v));
}
__device__ __forceinline__ void fma2a(u64 &acc, u64 a, u64 b) {
    asm("fma.rn.f32x2 %0, %1, %2, %0;" : "+l"(acc) : "l"(a), "l"(b));
}
__device__ __forceinline__ float hadd2(u64 v) {
    float a, b; unpack2(v, a, b); return a + b;
}

__device__ __forceinline__ float ex2f(float x) {
    float r; asm("ex2.approx.f32 %0, %1;" : "=f"(r) : "f"(x)); return r;
}
__device__ __forceinline__ float rcpf(float x) {
    float r; asm("rcp.approx.f32 %0, %1;" : "=f"(r) : "f"(x)); return r;
}
// sigmoid(x) = 1 / (1 + 2^(-x*log2e)); safe at both extremes (rcp(inf)=0).
__device__ __forceinline__ float sigm(float x) {
    return rcpf(1.0f + ex2f(-1.4426950408889634f * x));
}
// tanh(x) = sign(x)*(1-e)/(1+e), e = 2^(-2|x|*log2e); e<=1, no inf/NaN.
__device__ __forceinline__ float tanhx(float x) {
    float ax = fabsf(x);
    float e  = ex2f(-2.8853900817779268f * ax);
    float r  = (1.0f - e) * rcpf(1.0f + e);
    return copysignf(r, x);
}

// ---- prep: pack masked weights/biases into g_wbuf (then memcpy'd to cbuf) ----
__global__ void prep_kernel(
    const float* __restrict__ Wih, const float* __restrict__ Whh,
    const float* __restrict__ bih, const float* __restrict__ bhh,
    const float* __restrict__ Wlin, const float* __restrict__ blin,
    const float* __restrict__ mih, const float* __restrict__ mhh)
{
    int tid = threadIdx.x;   // 128 threads, 1 block
    for (int idx = tid; idx < DDIM * NP * 4; idx += 128) {
        int j = idx / 36, r = idx % 36, p = r / 4, q = r % 4;
        const float* W = (q < 2) ? Wih : Whh;
        const float* M = (q < 2) ? mih : mhh;
        int gA = (q & 1) ? (34 + j) : j;
        int gB = (q & 1) ? (51 + j) : (17 + j);
        int d0 = 2 * p, d1 = 2 * p + 1;
        float a0 = W[gA * DDIM + d0] * M[gA * DDIM + d0];
        float a1 = (d1 < DDIM) ? W[gA * DDIM + d1] * M[gA * DDIM + d1] : 0.0f;
        float b0 = W[gB * DDIM + d0] * M[gB * DDIM + d0];
        float b1 = (d1 < DDIM) ? W[gB * DDIM + d1] * M[gB * DDIM + d1] : 0.0f;
        g_wbuf[OFF_W + idx * 2 + 0] = pack2(a0, a1);
        g_wbuf[OFF_W + idx * 2 + 1] = pack2(b0, b1);
    }
    for (int idx = tid; idx < NP * NP; idx += 128) {
        int ccp = idx / NP, p = idx % NP;
        int c0 = 2 * ccp, c1 = 2 * ccp + 1;
        int d0 = 2 * p, d1 = 2 * p + 1;
        float x0 = Wlin[c0 * DDIM + d0];
        float x1 = (d1 < DDIM) ? Wlin[c0 * DDIM + d1] : 0.0f;
        float y0 = (c1 < DDIM) ? Wlin[c1 * DDIM + d0] : 0.0f;
        float y1 = (c1 < DDIM && d1 < DDIM) ? Wlin[c1 * DDIM + d1] : 0.0f;
        g_wbuf[OFF_LIN + idx * 2 + 0] = pack2(x0, x1);
        g_wbuf[OFF_LIN + idx * 2 + 1] = pack2(y0, y1);
    }
    if (tid < DDIM) {
        int j = tid;
        g_wbuf[OFF_B + j * 4 + 0] = pack2(bih[j]      + bhh[j],      0.0f);
        g_wbuf[OFF_B + j * 4 + 1] = pack2(bih[17 + j] + bhh[17 + j], 0.0f);
        g_wbuf[OFF_B + j * 4 + 2] = pack2(bih[34 + j] + bhh[34 + j], 0.0f);
        g_wbuf[OFF_B + j * 4 + 3] = pack2(bih[51 + j] + bhh[51 + j], 0.0f);
    }
    if (tid < 2 * NP) {
        int cc = tid;
        g_wbuf[OFF_BLIN + cc] = (cc < DDIM) ? pack2(blin[cc], 0.0f) : 0ull;
    }
}

__global__ void __launch_bounds__(TPB, 7) lstm_kernel(
    const float* __restrict__ x,     // [B, T, D]
    float* __restrict__ out)         // [B, TOUT, D]
{
    __shared__ float sStage[TPB * XROW];   // x / out staging only

    const int tid = threadIdx.x;
    const long bi0 = (long)blockIdx.x * TPB;
    const float* __restrict__ xg = x + bi0 * (TLEN * DDIM);
    float* __restrict__ og = out + bi0 * (TOUT * DDIM);
    const u64* __restrict__ sMyRow = (const u64*)(sStage + tid * XROW);

    u64 xi[NP], h[NP], hnew[NP];
    float c[DDIM];
#pragma unroll
    for (int p = 0; p < NP; p++) { xi[p] = 0ull; h[p] = 0ull; }
#pragma unroll
    for (int j = 0; j < DDIM; j++) c[j] = 0.0f;

#pragma unroll 1
    for (int t = 0; t < TLEN; t++) {
        if (t < SLBC) {
            __syncthreads();   // staging buffer free (prior readers done)
#pragma unroll
            for (int k = 0; k < DDIM; k++) {
                int idx = tid + k * TPB;             // coalesced
                int el = idx / DDIM, d = idx % DDIM;
                sStage[el * XROW + d] = xg[(long)el * (TLEN * DDIM) + t * DDIM + d];
            }
            __syncthreads();
#pragma unroll
            for (int p = 0; p < 8; p++) xi[p] = sMyRow[p];       // LDS.64
            {
                float lo, hi; unpack2(sMyRow[8], lo, hi);
                xi[8] = pack2(lo, 0.0f);
            }
        }

        // ---- LSTM cell: j-pairs, weights from __constant__ (LDCU path) ----
#pragma unroll
        for (int jj = 0; jj < 8; jj++) {
            const int j0 = 2 * jj, j1 = 2 * jj + 1;
            u64 ai0 = CB(j0, 0), af0 = CB(j0, 1), ag0 = CB(j0, 2), ao0 = CB(j0, 3);
            u64 ai1 = CB(j1, 0), af1 = CB(j1, 1), ag1 = CB(j1, 2), ao1 = CB(j1, 3);
#pragma unroll
            for (int p = 0; p < NP; p++) {
                u64 xp = xi[p], hp = h[p];
                fma2a(ai0, xp, CW(j0, p, 0, 0)); fma2a(af0, xp, CW(j0, p, 0, 1));
                fma2a(ag0, xp, CW(j0, p, 1, 0)); fma2a(ao0, xp, CW(j0, p, 1, 1));
                fma2a(ai1, xp, CW(j1, p, 0, 0)); fma2a(af1, xp, CW(j1, p, 0, 1));
                fma2a(ag1, xp, CW(j1, p, 1, 0)); fma2a(ao1, xp, CW(j1, p, 1, 1));
                fma2a(ai0, hp, CW(j0, p, 2, 0)); fma2a(af0, hp, CW(j0, p, 2, 1));
                fma2a(ag0, hp, CW(j0, p, 3, 0)); fma2a(ao0, hp, CW(j0, p, 3, 1));
                fma2a(ai1, hp, CW(j1, p, 2, 0)); fma2a(af1, hp, CW(j1, p, 2, 1));
                fma2a(ag1, hp, CW(j1, p, 3, 0)); fma2a(ao1, hp, CW(j1, p, 3, 1));
            }
            float hn0, hn1;
            {
                float gi = hadd2(ai0), gf = hadd2(af0), gg = hadd2(ag0), go = hadd2(ao0);
                float cn = fmaf(sigm(gf), c[j0], sigm(gi) * tanhx(gg));
                c[j0] = cn; hn0 = sigm(go) * tanhx(cn);
            }
            {
                float gi = hadd2(ai1), gf = hadd2(af1), gg = hadd2(ag1), go = hadd2(ao1);
                float cn = fmaf(sigm(gf), c[j1], sigm(gi) * tanhx(gg));
                c[j1] = cn; hn1 = sigm(go) * tanhx(cn);
            }
            hnew[jj] = pack2(hn0, hn1);
        }
        {   // tail j = 16
            const int j = 16;
            u64 ai = CB(j, 0), af = CB(j, 1), ag = CB(j, 2), ao = CB(j, 3);
#pragma unroll
            for (int p = 0; p < NP; p++) {
                u64 xp = xi[p], hp = h[p];
                fma2a(ai, xp, CW(j, p, 0, 0)); fma2a(af, xp, CW(j, p, 0, 1));
                fma2a(ag, xp, CW(j, p, 1, 0)); fma2a(ao, xp, CW(j, p, 1, 1));
                fma2a(ai, hp, CW(j, p, 2, 0)); fma2a(af, hp, CW(j, p, 2, 1));
                fma2a(ag, hp, CW(j, p, 3, 0)); fma2a(ao, hp, CW(j, p, 3, 1));
            }
            float gi = hadd2(ai), gf = hadd2(af), gg = hadd2(ag), go = hadd2(ao);
            float cn = fmaf(sigm(gf), c[j], sigm(gi) * tanhx(gg));
            c[j] = cn;
            hnew[8] = pack2(sigm(go) * tanhx(cn), 0.0f);
        }
#pragma unroll
        for (int p = 0; p < NP; p++) h[p] = hnew[p];

        if (t >= SLBC - 1) {
            float o[2 * NP];
#pragma unroll
            for (int ccp = 0; ccp < NP; ccp++) {
                u64 a0 = CBL(2 * ccp), a1 = CBL(2 * ccp + 1);
#pragma unroll
                for (int p = 0; p < NP; p++) {
                    fma2a(a0, h[p], CL(ccp, p, 0));
                    fma2a(a1, h[p], CL(ccp, p, 1));
                }
                o[2 * ccp] = hadd2(a0); o[2 * ccp + 1] = hadd2(a1);
            }
            if (t >= SLBC) {
                int tp = t - SLBC;
                __syncthreads();   // buffer free (prior step's STG readers done)
                u64* myRowW = (u64*)(sStage + tid * XROW);
#pragma unroll
                for (int p = 0; p < NP; p++)
                    myRowW[p] = pack2(o[2 * p], (2 * p + 1 < DDIM) ? o[2 * p + 1] : 0.0f);
                __syncthreads();
#pragma unroll
                for (int k = 0; k < DDIM; k++) {
                    int idx = tid + k * TPB;
                    int el = idx / DDIM, d = idx % DDIM;
                    og[(long)el * (TOUT * DDIM) + tp * DDIM + d] = sStage[el * XROW + d];
                }
            }
            // Feedback input for next step.
#pragma unroll
            for (int p = 0; p < 8; p++) xi[p] = pack2(o[2 * p], o[2 * p + 1]);
            xi[8] = pack2(o[16], 0.0f);
        }
    }
}

extern "C" void kernel_launch(void* const* d_in, const int* in_sizes, int n_in,
                              void* d_out, int out_size) {
    const float* x    = (const float*)d_in[0];
    const float* Wih  = (const float*)d_in[1];
    const float* Whh  = (const float*)d_in[2];
    const float* bih  = (const float*)d_in[3];
    const float* bhh  = (const float*)d_in[4];
    const float* Wlin = (const float*)d_in[5];
    const float* blin = (const float*)d_in[6];
    const float* mih  = (const float*)d_in[7];
    const float* mhh  = (const float*)d_in[8];
    float* out = (float*)d_out;

    // 1) pack weights into g_wbuf
    prep_kernel<<<1, 128>>>(Wih, Whh, bih, bhh, Wlin, blin, mih, mhh);
    // 2) D2D async copy into the constant bank (graph-capturable memcpy node)
    void* src = nullptr;
    cudaGetSymbolAddress(&src, g_wbuf);
    cudaMemcpyToSymbolAsync(cbuf, src, CBUF_N * sizeof(u64), 0,
                            cudaMemcpyDeviceToDevice, 0);
    // 3) main kernel
    dim3 grid(BSZ / TPB);   // 1024 CTAs of 64 threads
    dim3 block(TPB);
    lstm_kernel<<<grid, block>>>(x, out);
}